// round 1
// baseline (speedup 1.0000x reference)
#include <cuda_runtime.h>
#include <math.h>

#define NG   8
#define ND   16
#define NL   1024
#define NB   16
#define NE   8
#define NOUT 64
#define NKS  3
#define NK   4
#define NLP  1022
#define TILE 128
#define NTILES 8      // ceil(1022/128)
#define XPAD 132      // padded x row in smem (tile+2 -> 130, pad to 132 for float4 align)

// Scratch (static device globals — no allocation)
__device__ float g_gates[NG*NB*NE];
__device__ float g_weff[NG*NB*NOUT*NOUT];
__device__ float g_beff[NG*NB*NOUT];

__device__ __forceinline__ float cv_sq(const float* v) {
    float m = 0.f;
    #pragma unroll
    for (int i = 0; i < NE; i++) m += v[i];
    m *= (1.f / NE);
    float var = 0.f;
    #pragma unroll
    for (int i = 0; i < NE; i++) { float d = v[i] - m; var += d * d; }
    var *= (1.f / (NE - 1));            // ddof=1
    return var / (m * m + 1e-10f);
}

// ---------------------------------------------------------------------------
// Kernel A: gating. 1 block, 128 threads; thread t = (g = t/16, b = t%16).
// Computes gates, writes gates_out + loss into d_out, gates into scratch.
// ---------------------------------------------------------------------------
__global__ void gate_kernel(const float* __restrict__ x,
                            const float* __restrict__ w_gate,
                            float* __restrict__ out) {
    const int t = threadIdx.x;           // 0..127
    const int g = t >> 4;
    const int b = t & 15;

    // gate_in: xg[b, d, L-6 .. L-2]  (5 positions), flattened d*5+j
    float gin[ND * 5];
    #pragma unroll
    for (int d = 0; d < ND; d++)
        #pragma unroll
        for (int j = 0; j < 5; j++)
            gin[d * 5 + j] = x[(size_t)b * (NG * ND * NL)
                               + (size_t)(g * ND + d) * NL + (NL - 6 + j)];

    // logits = gate_in @ w_gate[g]   (80 x 8)
    float logit[NE];
    #pragma unroll
    for (int e = 0; e < NE; e++) logit[e] = 0.f;
    for (int i = 0; i < ND * 5; i++) {
        float gv = gin[i];
        const float* wrow = w_gate + (size_t)(g * ND * 5 + i) * NE;
        #pragma unroll
        for (int e = 0; e < NE; e++) logit[e] += gv * wrow[e];
    }

    // softmax over E
    float m = logit[0];
    #pragma unroll
    for (int e = 1; e < NE; e++) m = fmaxf(m, logit[e]);
    float p[NE]; float s = 0.f;
    #pragma unroll
    for (int e = 0; e < NE; e++) { p[e] = expf(logit[e] - m); s += p[e]; }
    float inv = 1.f / s;
    #pragma unroll
    for (int e = 0; e < NE; e++) p[e] *= inv;

    // top-4 (descending, lowest index on ties)
    float q[NE];
    #pragma unroll
    for (int e = 0; e < NE; e++) q[e] = p[e];
    float tv[NK]; int ti[NK];
    #pragma unroll
    for (int k = 0; k < NK; k++) {
        float best = -1e30f; int bi = 0;
        #pragma unroll
        for (int e = 0; e < NE; e++)
            if (q[e] > best) { best = q[e]; bi = e; }
        tv[k] = best; ti[k] = bi; q[bi] = -1e30f;
    }
    float dsum = tv[0] + tv[1] + tv[2] + tv[3] + 1e-6f;
    float gates[NE];
    #pragma unroll
    for (int e = 0; e < NE; e++) gates[e] = 0.f;
    #pragma unroll
    for (int k = 0; k < NK; k++) gates[ti[k]] = tv[k] / dsum;

    // write scratch gates + gates_out (shape (B, E, G))
    const size_t combine_sz = (size_t)NB * NG * NOUT * NLP;
    #pragma unroll
    for (int e = 0; e < NE; e++) {
        g_gates[(g * NB + b) * NE + e] = gates[e];
        out[combine_sz + 1 + (size_t)(b * NE + e) * NG + g] = gates[e];
    }

    // loss
    __shared__ float sg[NG * NB][NE];
    #pragma unroll
    for (int e = 0; e < NE; e++) sg[t][e] = gates[e];
    __syncthreads();

    __shared__ float lsum[NG];
    if (t < NG) {
        float imp[NE], ld[NE];
        #pragma unroll
        for (int e = 0; e < NE; e++) { imp[e] = 0.f; ld[e] = 0.f; }
        for (int bb = 0; bb < NB; bb++) {
            #pragma unroll
            for (int e = 0; e < NE; e++) {
                float v = sg[t * NB + bb][e];
                imp[e] += v;
                ld[e]  += (v > 0.f) ? 1.f : 0.f;
            }
        }
        lsum[t] = cv_sq(imp) + cv_sq(ld);
    }
    __syncthreads();
    if (t == 0) {
        float total = 0.f;
        #pragma unroll
        for (int i = 0; i < NG; i++) total += lsum[i];
        out[combine_sz] = 0.01f * total;
    }
}

// ---------------------------------------------------------------------------
// Kernel B: fold gates into conv2 weights.
// W_eff[g,b][o][i] = sum_e gates[e] * w2[g][o*E+e][i]
// ---------------------------------------------------------------------------
__global__ void weff_kernel(const float* __restrict__ w2,
                            const float* __restrict__ b2) {
    const int blk = blockIdx.x;          // g*NB + b
    const int g = blk >> 4;
    __shared__ float gs[NE];
    if (threadIdx.x < NE) gs[threadIdx.x] = g_gates[blk * NE + threadIdx.x];
    __syncthreads();

    const float* w2g = w2 + (size_t)g * NOUT * NE * NOUT;
    float* wef = g_weff + (size_t)blk * NOUT * NOUT;
    for (int idx = threadIdx.x; idx < NOUT * NOUT; idx += blockDim.x) {
        int o = idx >> 6, i = idx & 63;
        float acc = 0.f;
        #pragma unroll
        for (int e = 0; e < NE; e++)
            acc += gs[e] * w2g[(size_t)(o * NE + e) * NOUT + i];
        wef[idx] = acc;
    }
    if (threadIdx.x < NOUT) {
        int o = threadIdx.x;
        float acc = 0.f;
        #pragma unroll
        for (int e = 0; e < NE; e++)
            acc += gs[e] * b2[(size_t)g * NOUT * NE + o * NE + e];
        g_beff[blk * NOUT + o] = acc;
    }
}

// ---------------------------------------------------------------------------
// Kernel C: fused conv1 + tanh + (W_eff GEMM).
// grid (NTILES, NB, NG), 256 threads, dynamic smem.
// ---------------------------------------------------------------------------
__global__ void main_kernel(const float* __restrict__ x,
                            const float* __restrict__ w1,
                            const float* __restrict__ b1,
                            float* __restrict__ out) {
    const int tile = blockIdx.x;
    const int b    = blockIdx.y;
    const int g    = blockIdx.z;
    const int l0g  = tile * TILE;
    const int tlen = min(TILE, NLP - l0g);

    extern __shared__ float smem[];
    float* xs  = smem;                        // ND * XPAD        = 2112
    float* w1s = xs  + ND * XPAD;             // NOUT*ND*NKS      = 3072
    float* wes = w1s + NOUT * ND * NKS;       // NOUT*NOUT        = 4096
    float* hs  = wes + NOUT * NOUT;           // NOUT*TILE        = 8192
    float* bes = hs  + NOUT * TILE;           // NOUT
    float* b1s = bes + NOUT;                  // NOUT

    const int t = threadIdx.x;

    // ---- loads ----
    const float* xb = x + (size_t)b * (NG * ND * NL) + (size_t)g * ND * NL + l0g;
    const int ncols = tlen + 2;               // <= 130
    for (int idx = t; idx < ND * ncols; idx += 256) {
        int d = idx / ncols, c = idx % ncols;
        xs[d * XPAD + c] = xb[(size_t)d * NL + c];
    }
    const float* w1g = w1 + (size_t)g * NOUT * ND * NKS;
    for (int idx = t; idx < NOUT * ND * NKS; idx += 256) w1s[idx] = w1g[idx];
    const float* weg = g_weff + (size_t)(g * NB + b) * NOUT * NOUT;
    for (int idx = t; idx < NOUT * NOUT; idx += 256) wes[idx] = weg[idx];
    if (t < NOUT) bes[t] = g_beff[(g * NB + b) * NOUT + t];
    if (t >= 128 && t < 128 + NOUT) b1s[t - 128] = b1[g * NOUT + (t - 128)];
    __syncthreads();

    // ---- phase 2: h = tanh(conv1(x)) ----
    // thread -> (r = t/32 in 0..7, cg = t%32). Columns l0..l0+3, rows r, r+8, ...
    const int cg = t & 31;
    const int r  = t >> 5;
    const int l0 = cg * 4;
    #pragma unroll
    for (int oo = 0; oo < 8; oo++) {
        const int o = r + oo * 8;
        float a0 = b1s[o], a1 = a0, a2 = a0, a3 = a0;
        #pragma unroll
        for (int d = 0; d < ND; d++) {
            const float4 xa = *(const float4*)&xs[d * XPAD + l0];
            const float4 xc = *(const float4*)&xs[d * XPAD + l0 + 4];
            const float xv0 = xa.x, xv1 = xa.y, xv2 = xa.z, xv3 = xa.w;
            const float xv4 = xc.x, xv5 = xc.y;
            const float w0 = w1s[(o * ND + d) * NKS + 0];
            const float w1v = w1s[(o * ND + d) * NKS + 1];
            const float w2v = w1s[(o * ND + d) * NKS + 2];
            a0 += w0 * xv0 + w1v * xv1 + w2v * xv2;
            a1 += w0 * xv1 + w1v * xv2 + w2v * xv3;
            a2 += w0 * xv2 + w1v * xv3 + w2v * xv4;
            a3 += w0 * xv3 + w1v * xv4 + w2v * xv5;
        }
        *(float4*)&hs[o * TILE + l0] =
            make_float4(tanhf(a0), tanhf(a1), tanhf(a2), tanhf(a3));
    }
    __syncthreads();

    // ---- phase 3: out = W_eff @ h + b_eff ----
    // thread -> 8 rows (ob..ob+7) x 4 cols (l3..l3+3)
    const int l3 = (t & 31) * 4;
    const int ob = (t >> 5) * 8;
    float acc[8][4];
    #pragma unroll
    for (int i = 0; i < 8; i++) {
        float bv = bes[ob + i];
        #pragma unroll
        for (int j = 0; j < 4; j++) acc[i][j] = bv;
    }
    #pragma unroll 4
    for (int k = 0; k < NOUT; k++) {
        const float4 hv = *(const float4*)&hs[k * TILE + l3];
        #pragma unroll
        for (int i = 0; i < 8; i++) {
            const float w = wes[(ob + i) * NOUT + k];
            acc[i][0] += w * hv.x;
            acc[i][1] += w * hv.y;
            acc[i][2] += w * hv.z;
            acc[i][3] += w * hv.w;
        }
    }
    // store (combine_features: (B, G, OUT, LP))
    #pragma unroll
    for (int i = 0; i < 8; i++) {
        const int o = ob + i;
        float* orow = out + ((size_t)(b * NG + g) * NOUT + o) * NLP + l0g + l3;
        #pragma unroll
        for (int j = 0; j < 4; j++)
            if (l3 + j < tlen) orow[j] = acc[i][j];
    }
}

// ---------------------------------------------------------------------------
extern "C" void kernel_launch(void* const* d_in, const int* in_sizes, int n_in,
                              void* d_out, int out_size) {
    const float* x       = (const float*)d_in[0];
    const float* w_gate  = (const float*)d_in[1];
    const float* conv1_w = (const float*)d_in[2];
    const float* conv1_b = (const float*)d_in[3];
    const float* conv2_w = (const float*)d_in[4];
    const float* conv2_b = (const float*)d_in[5];
    float* out = (float*)d_out;

    const int smem_bytes = (ND * XPAD + NOUT * ND * NKS + NOUT * NOUT
                            + NOUT * TILE + 2 * NOUT) * sizeof(float);
    cudaFuncSetAttribute(main_kernel,
                         cudaFuncAttributeMaxDynamicSharedMemorySize, smem_bytes);

    gate_kernel<<<1, 128>>>(x, w_gate, out);
    weff_kernel<<<NG * NB, 256>>>(conv2_w, conv2_b);
    main_kernel<<<dim3(NTILES, NB, NG), 256, smem_bytes>>>(x, conv1_w, conv1_b, out);
}

// round 3
// speedup vs baseline: 1.2508x; 1.2508x over previous
#include <cuda_runtime.h>
#include <math.h>

#define NG   8
#define ND   16
#define NL   1024
#define NB   16
#define NE   8
#define NOUT 64
#define NKS  3
#define NK   4
#define NLP  1022
#define TILE 128
#define NTILES 8
#define XPAD 132

// Scratch (static device globals — no allocation)
__device__ float g_gates[NG*NB*NE];
__device__ float g_weff[NG*NB*NOUT*NOUT];   // stored TRANSPOSED: [g,b][i][o]
__device__ float g_beff[NG*NB*NOUT];

__device__ __forceinline__ float tanh_fast(float x) {
    float r;
    asm("tanh.approx.f32 %0, %1;" : "=f"(r) : "f"(x));
    return r;
}

__device__ __forceinline__ float cv_sq(const float* v) {
    float m = 0.f;
    #pragma unroll
    for (int i = 0; i < NE; i++) m += v[i];
    m *= (1.f / NE);
    float var = 0.f;
    #pragma unroll
    for (int i = 0; i < NE; i++) { float d = v[i] - m; var += d * d; }
    var *= (1.f / (NE - 1));
    return var / (m * m + 1e-10f);
}

// ---------------------------------------------------------------------------
// Kernel A: gating + W_eff, one block per (g,b). 128 threads.
// ---------------------------------------------------------------------------
__global__ __launch_bounds__(128)
void gateweff_kernel(const float* __restrict__ x,
                     const float* __restrict__ w_gate,
                     const float* __restrict__ w2,
                     const float* __restrict__ b2,
                     float* __restrict__ out) {
    const int blk = blockIdx.x;   // g*NB + b
    const int g = blk >> 4;
    const int b = blk & 15;
    const int t = threadIdx.x;

    __shared__ float gin[ND * 5];
    __shared__ float logits[NE];
    __shared__ float gs[NE];
    __shared__ float wef_s[NOUT * 65];   // [o][i] padded -> conflict-free transpose

    // gate inputs: xg[b, d, NL-6 .. NL-2]
    if (t < ND * 5) {
        int d = t / 5, j = t % 5;
        gin[t] = x[(size_t)b * (NG * ND * NL) + (size_t)(g * ND + d) * NL + (NL - 6 + j)];
    }
    __syncthreads();

    if (t < NE) {
        float acc = 0.f;
        const float* wg = w_gate + (size_t)g * ND * 5 * NE + t;
        #pragma unroll 8
        for (int i = 0; i < ND * 5; i++) acc += gin[i] * wg[i * NE];
        logits[t] = acc;
    }
    __syncthreads();

    if (t == 0) {
        float m = logits[0];
        #pragma unroll
        for (int e = 1; e < NE; e++) m = fmaxf(m, logits[e]);
        float p[NE]; float s = 0.f;
        #pragma unroll
        for (int e = 0; e < NE; e++) { p[e] = __expf(logits[e] - m); s += p[e]; }
        float inv = 1.f / s;
        #pragma unroll
        for (int e = 0; e < NE; e++) p[e] *= inv;

        float q[NE];
        #pragma unroll
        for (int e = 0; e < NE; e++) q[e] = p[e];
        float tv[NK]; int ti[NK];
        #pragma unroll
        for (int k = 0; k < NK; k++) {
            float best = -1e30f; int bi = 0;
            #pragma unroll
            for (int e = 0; e < NE; e++)
                if (q[e] > best) { best = q[e]; bi = e; }
            tv[k] = best; ti[k] = bi; q[bi] = -1e30f;
        }
        float dsum = tv[0] + tv[1] + tv[2] + tv[3] + 1e-6f;
        float gates[NE];
        #pragma unroll
        for (int e = 0; e < NE; e++) gates[e] = 0.f;
        #pragma unroll
        for (int k = 0; k < NK; k++) gates[ti[k]] = tv[k] / dsum;

        const size_t combine_sz = (size_t)NB * NG * NOUT * NLP;
        #pragma unroll
        for (int e = 0; e < NE; e++) {
            gs[e] = gates[e];
            g_gates[blk * NE + e] = gates[e];
            out[combine_sz + 1 + (size_t)(b * NE + e) * NG + g] = gates[e];
        }
    }
    __syncthreads();

    // W_eff[o][i] = sum_e gs[e] * w2[g][o*E+e][i]
    const float* w2g = w2 + (size_t)g * NOUT * NE * NOUT;
    for (int idx = t; idx < NOUT * NOUT; idx += 128) {
        int o = idx >> 6, i = idx & 63;
        float acc = 0.f;
        #pragma unroll
        for (int e = 0; e < NE; e++)
            acc += gs[e] * w2g[(size_t)(o * NE + e) * NOUT + i];
        wef_s[o * 65 + i] = acc;
    }
    if (t < NOUT) {
        float acc = 0.f;
        #pragma unroll
        for (int e = 0; e < NE; e++)
            acc += gs[e] * b2[(size_t)g * NOUT * NE + t * NE + e];
        g_beff[blk * NOUT + t] = acc;
    }
    __syncthreads();

    // write W_eff TRANSPOSED: g_weff[blk][i][o]
    float* wef = g_weff + (size_t)blk * NOUT * NOUT;
    for (int idx = t; idx < NOUT * NOUT; idx += 128) {
        int i = idx >> 6, o = idx & 63;
        wef[idx] = wef_s[o * 65 + i];
    }
}

// ---------------------------------------------------------------------------
// Kernel B (trailing): loss from g_gates. 1 block, 64 threads.
// ---------------------------------------------------------------------------
__global__ void loss_kernel(float* __restrict__ out) {
    const int t = threadIdx.x;
    __shared__ float lsum[NG];
    if (t < NG) {
        float imp[NE], ld[NE];
        #pragma unroll
        for (int e = 0; e < NE; e++) { imp[e] = 0.f; ld[e] = 0.f; }
        for (int bb = 0; bb < NB; bb++) {
            #pragma unroll
            for (int e = 0; e < NE; e++) {
                float v = g_gates[(t * NB + bb) * NE + e];
                imp[e] += v;
                ld[e]  += (v > 0.f) ? 1.f : 0.f;
            }
        }
        lsum[t] = cv_sq(imp) + cv_sq(ld);
    }
    __syncthreads();
    if (t == 0) {
        float total = 0.f;
        #pragma unroll
        for (int i = 0; i < NG; i++) total += lsum[i];
        out[(size_t)NB * NG * NOUT * NLP] = 0.01f * total;
    }
}

// ---------------------------------------------------------------------------
// Kernel C: fused conv1 + tanh + W_eff GEMM.
// grid (NTILES, NB, NG), 256 threads. Warp w owns 8 contiguous out-channels;
// lane c owns 4 columns -> all weight LDS are broadcast .128.
// ---------------------------------------------------------------------------
__global__ __launch_bounds__(256)
void main_kernel(const float* __restrict__ x,
                 const float* __restrict__ w1,
                 const float* __restrict__ b1,
                 float* __restrict__ out) {
    const int tile = blockIdx.x;
    const int b    = blockIdx.y;
    const int g    = blockIdx.z;
    const int l0g  = tile * TILE;
    const int tlen = min(TILE, NLP - l0g);

    extern __shared__ float smem[];
    float* xs  = smem;                         // ND * XPAD   = 2112
    float* w1t = xs  + ND * XPAD;              // [d*3+k][o]  = 3072
    float* wet = w1t + ND * NKS * NOUT;        // [k][o]      = 4096
    float* hs  = wet + NOUT * NOUT;            // [o][l]      = 8192
    float* bes = hs  + NOUT * TILE;            // 64
    float* b1s = bes + NOUT;                   // 64

    const int t = threadIdx.x;
    const int c = t & 31;          // lane
    const int r = t >> 5;          // warp id = o-block
    const int ob = r * 8;          // 8 contiguous output channels
    const int l0 = c * 4;          // 4 columns

    // ---- cooperative loads ----
    const float* xb = x + (size_t)b * (NG * ND * NL) + (size_t)g * ND * NL + l0g;
    const int ncols = min(TILE + 2, NL - l0g);
    for (int idx = t; idx < ND * XPAD; idx += 256) {
        int d = idx / XPAD, cc = idx % XPAD;
        xs[idx] = (cc < ncols) ? xb[(size_t)d * NL + cc] : 0.f;
    }
    // w1 transpose: w1t[(d*3+k)*64 + o] = w1[g][o][d][k]
    const float* w1g = w1 + (size_t)g * NOUT * ND * NKS;
    for (int idx = t; idx < NOUT * ND * NKS; idx += 256) {
        int o = idx / (ND * NKS), dk = idx % (ND * NKS);
        w1t[dk * NOUT + o] = w1g[idx];
    }
    // W_eff^T already in [i][o] layout: straight coalesced copy
    const float* weg = g_weff + (size_t)(g * NB + b) * NOUT * NOUT;
    for (int idx = t; idx < NOUT * NOUT; idx += 256) wet[idx] = weg[idx];
    if (t < NOUT) bes[t] = g_beff[(g * NB + b) * NOUT + t];
    if (t >= 128 && t < 128 + NOUT) b1s[t - 128] = b1[g * NOUT + (t - 128)];
    __syncthreads();

    // ---- phase 2: h = tanh(conv1(x)) ; thread computes 8 o x 4 cols ----
    {
        float acc[8][4];
        #pragma unroll
        for (int i = 0; i < 8; i++) {
            float bv = b1s[ob + i];
            #pragma unroll
            for (int j = 0; j < 4; j++) acc[i][j] = bv;
        }
        #pragma unroll
        for (int d = 0; d < ND; d++) {
            const float4 xa = *(const float4*)&xs[d * XPAD + l0];
            const float4 xc = *(const float4*)&xs[d * XPAD + l0 + 4];
            float xv[6] = {xa.x, xa.y, xa.z, xa.w, xc.x, xc.y};
            #pragma unroll
            for (int k = 0; k < NKS; k++) {
                const float4 wa = *(const float4*)&w1t[(d * NKS + k) * NOUT + ob];
                const float4 wb = *(const float4*)&w1t[(d * NKS + k) * NOUT + ob + 4];
                const float wv[8] = {wa.x, wa.y, wa.z, wa.w, wb.x, wb.y, wb.z, wb.w};
                #pragma unroll
                for (int i = 0; i < 8; i++) {
                    acc[i][0] += wv[i] * xv[k + 0];
                    acc[i][1] += wv[i] * xv[k + 1];
                    acc[i][2] += wv[i] * xv[k + 2];
                    acc[i][3] += wv[i] * xv[k + 3];
                }
            }
        }
        #pragma unroll
        for (int i = 0; i < 8; i++)
            *(float4*)&hs[(ob + i) * TILE + l0] =
                make_float4(tanh_fast(acc[i][0]), tanh_fast(acc[i][1]),
                            tanh_fast(acc[i][2]), tanh_fast(acc[i][3]));
    }
    __syncthreads();

    // ---- phase 3: out = W_eff @ h + b_eff ; same 8x4 thread tile ----
    float acc[8][4];
    #pragma unroll
    for (int i = 0; i < 8; i++) {
        float bv = bes[ob + i];
        #pragma unroll
        for (int j = 0; j < 4; j++) acc[i][j] = bv;
    }
    #pragma unroll 4
    for (int k = 0; k < NOUT; k++) {
        const float4 hv = *(const float4*)&hs[k * TILE + l0];
        const float4 wa = *(const float4*)&wet[k * NOUT + ob];
        const float4 wb = *(const float4*)&wet[k * NOUT + ob + 4];
        const float wv[8] = {wa.x, wa.y, wa.z, wa.w, wb.x, wb.y, wb.z, wb.w};
        #pragma unroll
        for (int i = 0; i < 8; i++) {
            acc[i][0] += wv[i] * hv.x;
            acc[i][1] += wv[i] * hv.y;
            acc[i][2] += wv[i] * hv.z;
            acc[i][3] += wv[i] * hv.w;
        }
    }

    // store (combine_features: (B, G, OUT, LP)); NLP=1022 -> rows only 8B-aligned,
    // so use float2 stores (l0g+l0 is even, NLP is even => always 8B-aligned).
    if (tlen == TILE) {
        #pragma unroll
        for (int i = 0; i < 8; i++) {
            float* orow = out + ((size_t)(b * NG + g) * NOUT + (ob + i)) * NLP + l0g + l0;
            *(float2*)(orow)     = make_float2(acc[i][0], acc[i][1]);
            *(float2*)(orow + 2) = make_float2(acc[i][2], acc[i][3]);
        }
    } else {
        #pragma unroll
        for (int i = 0; i < 8; i++) {
            float* orow = out + ((size_t)(b * NG + g) * NOUT + (ob + i)) * NLP + l0g + l0;
            #pragma unroll
            for (int j = 0; j < 4; j++)
                if (l0 + j < tlen) orow[j] = acc[i][j];
        }
    }
}

// ---------------------------------------------------------------------------
extern "C" void kernel_launch(void* const* d_in, const int* in_sizes, int n_in,
                              void* d_out, int out_size) {
    const float* x       = (const float*)d_in[0];
    const float* w_gate  = (const float*)d_in[1];
    const float* conv1_w = (const float*)d_in[2];
    const float* conv1_b = (const float*)d_in[3];
    const float* conv2_w = (const float*)d_in[4];
    const float* conv2_b = (const float*)d_in[5];
    float* out = (float*)d_out;

    const int smem_bytes = (ND * XPAD + ND * NKS * NOUT + NOUT * NOUT
                            + NOUT * TILE + 2 * NOUT) * sizeof(float);
    cudaFuncSetAttribute(main_kernel,
                         cudaFuncAttributeMaxDynamicSharedMemorySize, smem_bytes);

    gateweff_kernel<<<NG * NB, 128>>>(x, w_gate, conv2_w, conv2_b, out);
    main_kernel<<<dim3(NTILES, NB, NG), 256, smem_bytes>>>(x, conv1_w, conv1_b, out);
    loss_kernel<<<1, 64>>>(out);
}

// round 4
// speedup vs baseline: 1.4853x; 1.1875x over previous
#include <cuda_runtime.h>
#include <math.h>

#define NG   8
#define ND   16
#define NL   1024
#define NB   16
#define NE   8
#define NOUT 64
#define NKS  3
#define NK   4
#define NLP  1022
#define TILE 128
#define NTILES 8
#define XPAD 132
#define WETP 68            // padded W_eff row (mult of 4 -> float4-aligned)

// Scratch (static device global — no allocation)
__device__ float g_gates[NG*NB*NE];

__device__ __forceinline__ float tanh_fast(float x) {
    float r;
    asm("tanh.approx.f32 %0, %1;" : "=f"(r) : "f"(x));
    return r;
}

__device__ __forceinline__ float cv_sq(const float* v) {
    float m = 0.f;
    #pragma unroll
    for (int i = 0; i < NE; i++) m += v[i];
    m *= (1.f / NE);
    float var = 0.f;
    #pragma unroll
    for (int i = 0; i < NE; i++) { float d = v[i] - m; var += d * d; }
    var *= (1.f / (NE - 1));
    return var / (m * m + 1e-10f);
}

// ---------------------------------------------------------------------------
// Kernel A: gates only. 128 blocks x 1 warp; warp-parallel logits.
// ---------------------------------------------------------------------------
__global__ __launch_bounds__(32)
void gates_kernel(const float* __restrict__ x,
                  const float* __restrict__ w_gate,
                  float* __restrict__ out) {
    const int blk = blockIdx.x;   // g*NB + b
    const int g = blk >> 4;
    const int b = blk & 15;
    const int lane = threadIdx.x;

    float plog[NE];
    #pragma unroll
    for (int e = 0; e < NE; e++) plog[e] = 0.f;

    // i = d*5+j over 80 gate inputs; lanes stride 32
    #pragma unroll
    for (int i = lane; i < ND * 5; i += 32) {
        int d = i / 5, j = i % 5;
        float xv = x[(size_t)b * (NG * ND * NL) + (size_t)(g * ND + d) * NL + (NL - 6 + j)];
        const float4* w4 = (const float4*)(w_gate + ((size_t)g * ND * 5 + i) * NE);
        float4 wa = w4[0], wb = w4[1];
        plog[0] += xv * wa.x; plog[1] += xv * wa.y;
        plog[2] += xv * wa.z; plog[3] += xv * wa.w;
        plog[4] += xv * wb.x; plog[5] += xv * wb.y;
        plog[6] += xv * wb.z; plog[7] += xv * wb.w;
    }
    #pragma unroll
    for (int off = 16; off >= 1; off >>= 1)
        #pragma unroll
        for (int e = 0; e < NE; e++)
            plog[e] += __shfl_xor_sync(0xffffffffu, plog[e], off);

    if (lane == 0) {
        float m = plog[0];
        #pragma unroll
        for (int e = 1; e < NE; e++) m = fmaxf(m, plog[e]);
        float p[NE]; float s = 0.f;
        #pragma unroll
        for (int e = 0; e < NE; e++) { p[e] = __expf(plog[e] - m); s += p[e]; }
        float inv = 1.f / s;
        #pragma unroll
        for (int e = 0; e < NE; e++) p[e] *= inv;

        float q[NE];
        #pragma unroll
        for (int e = 0; e < NE; e++) q[e] = p[e];
        float tv[NK]; int ti[NK];
        #pragma unroll
        for (int k = 0; k < NK; k++) {
            float best = -1e30f; int bi = 0;
            #pragma unroll
            for (int e = 0; e < NE; e++)
                if (q[e] > best) { best = q[e]; bi = e; }
            tv[k] = best; ti[k] = bi; q[bi] = -1e30f;
        }
        float dsum = tv[0] + tv[1] + tv[2] + tv[3] + 1e-6f;
        float gates[NE];
        #pragma unroll
        for (int e = 0; e < NE; e++) gates[e] = 0.f;
        #pragma unroll
        for (int k = 0; k < NK; k++) gates[ti[k]] = tv[k] / dsum;

        const size_t combine_sz = (size_t)NB * NG * NOUT * NLP;
        #pragma unroll
        for (int e = 0; e < NE; e++) {
            g_gates[blk * NE + e] = gates[e];
            out[combine_sz + 1 + (size_t)(b * NE + e) * NG + g] = gates[e];
        }
    }
}

// ---------------------------------------------------------------------------
// Kernel B (trailing): loss from g_gates. 1 block, 64 threads.
// ---------------------------------------------------------------------------
__global__ void loss_kernel(float* __restrict__ out) {
    const int t = threadIdx.x;
    __shared__ float lsum[NG];
    if (t < NG) {
        float imp[NE], ld[NE];
        #pragma unroll
        for (int e = 0; e < NE; e++) { imp[e] = 0.f; ld[e] = 0.f; }
        for (int bb = 0; bb < NB; bb++) {
            #pragma unroll
            for (int e = 0; e < NE; e++) {
                float v = g_gates[(t * NB + bb) * NE + e];
                imp[e] += v;
                ld[e]  += (v > 0.f) ? 1.f : 0.f;
            }
        }
        lsum[t] = cv_sq(imp) + cv_sq(ld);
    }
    __syncthreads();
    if (t == 0) {
        float total = 0.f;
        #pragma unroll
        for (int i = 0; i < NG; i++) total += lsum[i];
        out[(size_t)NB * NG * NOUT * NLP] = 0.01f * total;
    }
}

// ---------------------------------------------------------------------------
// Kernel C: fused W_eff fold + conv1 + tanh + GEMM.
// grid (NTILES, NB, NG), 256 threads. Warp w owns 8 contiguous out-channels;
// lane c owns 4 columns -> weight LDS are broadcast .128.
// ---------------------------------------------------------------------------
__global__ __launch_bounds__(256)
void main_kernel(const float* __restrict__ x,
                 const float* __restrict__ w1,
                 const float* __restrict__ b1,
                 const float* __restrict__ w2,
                 const float* __restrict__ b2,
                 float* __restrict__ out) {
    const int tile = blockIdx.x;
    const int b    = blockIdx.y;
    const int g    = blockIdx.z;
    const int l0g  = tile * TILE;
    const int tlen = min(TILE, NLP - l0g);

    extern __shared__ float smem[];
    float* xs  = smem;                         // ND * XPAD    = 2112
    float* w1t = xs  + ND * XPAD;              // [d*3+k][o]   = 3072
    float* wet = w1t + ND * NKS * NOUT;        // [i][o] pad68 = 4352
    float* hs  = wet + NOUT * WETP;            // [o][l]       = 8192
    float* bes = hs  + NOUT * TILE;            // 64
    float* b1s = bes + NOUT;                   // 64

    const int t = threadIdx.x;
    const int c = t & 31;          // lane
    const int r = t >> 5;          // warp id = o-block
    const int ob = r * 8;          // 8 contiguous output channels
    const int l0 = c * 4;          // 4 columns

    // gates for this (g,b): uniform-address loads (L1 broadcast)
    const float* gp = g_gates + (size_t)(g * NB + b) * NE;
    float gv[NE];
    #pragma unroll
    for (int e = 0; e < NE; e++) gv[e] = __ldg(gp + e);

    // ---- cooperative loads ----
    const float* xb = x + (size_t)b * (NG * ND * NL) + (size_t)g * ND * NL + l0g;
    const int ncols = min(TILE + 2, NL - l0g);
    for (int idx = t; idx < ND * XPAD; idx += 256) {
        int d = idx / XPAD, cc = idx % XPAD;
        xs[idx] = (cc < ncols) ? xb[(size_t)d * NL + cc] : 0.f;
    }
    // w1 transpose: w1t[(d*3+k)*64 + o] = w1[g][o][d][k]
    const float* w1g = w1 + (size_t)g * NOUT * ND * NKS;
    for (int idx = t; idx < NOUT * ND * NKS; idx += 256) {
        int o = idx / (ND * NKS), dk = idx % (ND * NKS);
        w1t[dk * NOUT + o] = w1g[idx];
    }
    // W_eff fold: wet[i*WETP+o] = sum_e gv[e] * w2[g][o*E+e][i]  (coalesced reads)
    const float* w2g = w2 + (size_t)g * NOUT * NE * NOUT;
    #pragma unroll
    for (int it = 0; it < (NOUT * NOUT) / 256; it++) {
        int idx = t + it * 256;
        int o = idx >> 6, i = idx & 63;
        const float* wrow = w2g + (size_t)o * NE * NOUT + i;
        float acc = 0.f;
        #pragma unroll
        for (int e = 0; e < NE; e++) acc += gv[e] * wrow[e * NOUT];
        wet[i * WETP + o] = acc;
    }
    if (t < NOUT) {
        const float* brow = b2 + (size_t)g * NOUT * NE + t * NE;
        float acc = 0.f;
        #pragma unroll
        for (int e = 0; e < NE; e++) acc += gv[e] * brow[e];
        bes[t] = acc;
        b1s[t] = b1[g * NOUT + t];
    }
    __syncthreads();

    // ---- phase 2: h = tanh(conv1(x)) ; thread computes 8 o x 4 cols ----
    {
        float acc[8][4];
        #pragma unroll
        for (int i = 0; i < 8; i++) {
            float bv = b1s[ob + i];
            #pragma unroll
            for (int j = 0; j < 4; j++) acc[i][j] = bv;
        }
        #pragma unroll
        for (int d = 0; d < ND; d++) {
            const float4 xa = *(const float4*)&xs[d * XPAD + l0];
            const float4 xc = *(const float4*)&xs[d * XPAD + l0 + 4];
            float xv[6] = {xa.x, xa.y, xa.z, xa.w, xc.x, xc.y};
            #pragma unroll
            for (int k = 0; k < NKS; k++) {
                const float4 wa = *(const float4*)&w1t[(d * NKS + k) * NOUT + ob];
                const float4 wb = *(const float4*)&w1t[(d * NKS + k) * NOUT + ob + 4];
                const float wv[8] = {wa.x, wa.y, wa.z, wa.w, wb.x, wb.y, wb.z, wb.w};
                #pragma unroll
                for (int i = 0; i < 8; i++) {
                    acc[i][0] += wv[i] * xv[k + 0];
                    acc[i][1] += wv[i] * xv[k + 1];
                    acc[i][2] += wv[i] * xv[k + 2];
                    acc[i][3] += wv[i] * xv[k + 3];
                }
            }
        }
        #pragma unroll
        for (int i = 0; i < 8; i++)
            *(float4*)&hs[(ob + i) * TILE + l0] =
                make_float4(tanh_fast(acc[i][0]), tanh_fast(acc[i][1]),
                            tanh_fast(acc[i][2]), tanh_fast(acc[i][3]));
    }
    __syncthreads();

    // ---- phase 3: out = W_eff @ h + b_eff ; same 8x4 thread tile ----
    float acc[8][4];
    #pragma unroll
    for (int i = 0; i < 8; i++) {
        float bv = bes[ob + i];
        #pragma unroll
        for (int j = 0; j < 4; j++) acc[i][j] = bv;
    }
    #pragma unroll 4
    for (int k = 0; k < NOUT; k++) {
        const float4 hv = *(const float4*)&hs[k * TILE + l0];
        const float4 wa = *(const float4*)&wet[k * WETP + ob];
        const float4 wb = *(const float4*)&wet[k * WETP + ob + 4];
        const float wv[8] = {wa.x, wa.y, wa.z, wa.w, wb.x, wb.y, wb.z, wb.w};
        #pragma unroll
        for (int i = 0; i < 8; i++) {
            acc[i][0] += wv[i] * hv.x;
            acc[i][1] += wv[i] * hv.y;
            acc[i][2] += wv[i] * hv.z;
            acc[i][3] += wv[i] * hv.w;
        }
    }

    // store (combine_features: (B, G, OUT, LP)); rows 8B-aligned -> float2 stores
    if (tlen == TILE) {
        #pragma unroll
        for (int i = 0; i < 8; i++) {
            float* orow = out + ((size_t)(b * NG + g) * NOUT + (ob + i)) * NLP + l0g + l0;
            *(float2*)(orow)     = make_float2(acc[i][0], acc[i][1]);
            *(float2*)(orow + 2) = make_float2(acc[i][2], acc[i][3]);
        }
    } else {
        #pragma unroll
        for (int i = 0; i < 8; i++) {
            float* orow = out + ((size_t)(b * NG + g) * NOUT + (ob + i)) * NLP + l0g + l0;
            #pragma unroll
            for (int j = 0; j < 4; j++)
                if (l0 + j < tlen) orow[j] = acc[i][j];
        }
    }
}

// ---------------------------------------------------------------------------
extern "C" void kernel_launch(void* const* d_in, const int* in_sizes, int n_in,
                              void* d_out, int out_size) {
    const float* x       = (const float*)d_in[0];
    const float* w_gate  = (const float*)d_in[1];
    const float* conv1_w = (const float*)d_in[2];
    const float* conv1_b = (const float*)d_in[3];
    const float* conv2_w = (const float*)d_in[4];
    const float* conv2_b = (const float*)d_in[5];
    float* out = (float*)d_out;

    const int smem_bytes = (ND * XPAD + ND * NKS * NOUT + NOUT * WETP
                            + NOUT * TILE + 2 * NOUT) * sizeof(float);
    cudaFuncSetAttribute(main_kernel,
                         cudaFuncAttributeMaxDynamicSharedMemorySize, smem_bytes);

    gates_kernel<<<NG * NB, 32>>>(x, w_gate, out);
    main_kernel<<<dim3(NTILES, NB, NG), 256, smem_bytes>>>(x, conv1_w, conv1_b,
                                                           conv2_w, conv2_b, out);
    loss_kernel<<<1, 64>>>(out);
}

// round 5
// speedup vs baseline: 1.6119x; 1.0853x over previous
#include <cuda_runtime.h>
#include <math.h>

#define NG   8
#define ND   16
#define NL   1024
#define NB   16
#define NE   8
#define NOUT 64
#define NKS  3
#define NK   4
#define NLP  1022
#define TILE 128
#define NTILES 8
#define XPAD 132
#define WETP 68            // padded W_eff row (mult of 4 -> 16B-aligned rows)

typedef unsigned long long u64;

// Scratch (static device global — no allocation)
__device__ float g_gates[NG*NB*NE];

__device__ __forceinline__ float tanh_fast(float x) {
    float r;
    asm("tanh.approx.f32 %0, %1;" : "=f"(r) : "f"(x));
    return r;
}
// packed f32x2 fma: d.lo += a.lo*b.lo ; d.hi += a.hi*b.hi  (FFMA2 on sm_103a)
__device__ __forceinline__ void ffma2(u64& d, u64 a, u64 b) {
    asm("fma.rn.f32x2 %0, %1, %2, %0;" : "+l"(d) : "l"(a), "l"(b));
}
__device__ __forceinline__ u64 pack_dup(float x) {
    u64 r; asm("mov.b64 %0, {%1, %1};" : "=l"(r) : "f"(x)); return r;
}
__device__ __forceinline__ float2 unpack2(u64 v) {
    float2 f; asm("mov.b64 {%0, %1}, %2;" : "=f"(f.x), "=f"(f.y) : "l"(v)); return f;
}

__device__ __forceinline__ float cv_sq(const float* v) {
    float m = 0.f;
    #pragma unroll
    for (int i = 0; i < NE; i++) m += v[i];
    m *= (1.f / NE);
    float var = 0.f;
    #pragma unroll
    for (int i = 0; i < NE; i++) { float d = v[i] - m; var += d * d; }
    var *= (1.f / (NE - 1));
    return var / (m * m + 1e-10f);
}

// ---------------------------------------------------------------------------
// loss kernel (trailing): reads g_gates written by tile-0 main blocks.
// ---------------------------------------------------------------------------
__global__ void loss_kernel(float* __restrict__ out) {
    const int t = threadIdx.x;
    __shared__ float lsum[NG];
    if (t < NG) {
        float imp[NE], ld[NE];
        #pragma unroll
        for (int e = 0; e < NE; e++) { imp[e] = 0.f; ld[e] = 0.f; }
        for (int bb = 0; bb < NB; bb++) {
            #pragma unroll
            for (int e = 0; e < NE; e++) {
                float v = g_gates[(t * NB + bb) * NE + e];
                imp[e] += v;
                ld[e]  += (v > 0.f) ? 1.f : 0.f;
            }
        }
        lsum[t] = cv_sq(imp) + cv_sq(ld);
    }
    __syncthreads();
    if (t == 0) {
        float total = 0.f;
        #pragma unroll
        for (int i = 0; i < NG; i++) total += lsum[i];
        out[(size_t)NB * NG * NOUT * NLP] = 0.01f * total;
    }
}

// ---------------------------------------------------------------------------
// Main kernel: gates (warp 0, redundant per block) + W_eff fold + conv1 +
// tanh + GEMM, all FFMA2-packed over channel pairs.
// grid (NTILES, NB, NG), 256 threads.
// ---------------------------------------------------------------------------
__global__ __launch_bounds__(256)
void main_kernel(const float* __restrict__ x,
                 const float* __restrict__ w_gate,
                 const float* __restrict__ w1,
                 const float* __restrict__ b1,
                 const float* __restrict__ w2,
                 const float* __restrict__ b2,
                 float* __restrict__ out) {
    const int tile = blockIdx.x;
    const int b    = blockIdx.y;
    const int g    = blockIdx.z;
    const int l0g  = tile * TILE;
    const int tlen = min(TILE, NLP - l0g);

    extern __shared__ float smem[];
    float* xs  = smem;                         // ND * XPAD    = 2112
    float* w1t = xs  + ND * XPAD;              // [d*3+k][o]   = 3072
    float* wet = w1t + ND * NKS * NOUT;        // [i][o] pad68 = 4352
    float* hs  = wet + NOUT * WETP;            // [o][l]       = 8192
    float* bes = hs  + NOUT * TILE;            // 64
    float* b1s = bes + NOUT;                   // 64
    float* gsm = b1s + NOUT;                   // 8 gates

    const int t = threadIdx.x;
    const int c = t & 31;          // lane
    const int r = t >> 5;          // warp id = o-block
    const int ob = r * 8;          // 8 contiguous output channels
    const int l0 = c * 4;          // 4 columns

    // ---- warp 0: compute gates for (g,b) ----
    if (r == 0) {
        float plog[NE];
        #pragma unroll
        for (int e = 0; e < NE; e++) plog[e] = 0.f;
        #pragma unroll
        for (int i = c; i < ND * 5; i += 32) {
            int d = i / 5, j = i % 5;
            float xv = x[(size_t)b * (NG * ND * NL) + (size_t)(g * ND + d) * NL + (NL - 6 + j)];
            const float4* w4 = (const float4*)(w_gate + ((size_t)g * ND * 5 + i) * NE);
            float4 wa = w4[0], wb = w4[1];
            plog[0] += xv * wa.x; plog[1] += xv * wa.y;
            plog[2] += xv * wa.z; plog[3] += xv * wa.w;
            plog[4] += xv * wb.x; plog[5] += xv * wb.y;
            plog[6] += xv * wb.z; plog[7] += xv * wb.w;
        }
        #pragma unroll
        for (int off = 16; off >= 1; off >>= 1)
            #pragma unroll
            for (int e = 0; e < NE; e++)
                plog[e] += __shfl_xor_sync(0xffffffffu, plog[e], off);

        if (c == 0) {
            float m = plog[0];
            #pragma unroll
            for (int e = 1; e < NE; e++) m = fmaxf(m, plog[e]);
            float p[NE]; float s = 0.f;
            #pragma unroll
            for (int e = 0; e < NE; e++) { p[e] = __expf(plog[e] - m); s += p[e]; }
            float inv = 1.f / s;
            #pragma unroll
            for (int e = 0; e < NE; e++) p[e] *= inv;

            float q[NE];
            #pragma unroll
            for (int e = 0; e < NE; e++) q[e] = p[e];
            float tv[NK]; int ti[NK];
            #pragma unroll
            for (int k = 0; k < NK; k++) {
                float best = -1e30f; int bi = 0;
                #pragma unroll
                for (int e = 0; e < NE; e++)
                    if (q[e] > best) { best = q[e]; bi = e; }
                tv[k] = best; ti[k] = bi; q[bi] = -1e30f;
            }
            float dsum = tv[0] + tv[1] + tv[2] + tv[3] + 1e-6f;
            float gates[NE];
            #pragma unroll
            for (int e = 0; e < NE; e++) gates[e] = 0.f;
            #pragma unroll
            for (int k = 0; k < NK; k++) gates[ti[k]] = tv[k] / dsum;

            #pragma unroll
            for (int e = 0; e < NE; e++) gsm[e] = gates[e];
            if (tile == 0) {
                const size_t combine_sz = (size_t)NB * NG * NOUT * NLP;
                #pragma unroll
                for (int e = 0; e < NE; e++) {
                    g_gates[(g * NB + b) * NE + e] = gates[e];
                    out[combine_sz + 1 + (size_t)(b * NE + e) * NG + g] = gates[e];
                }
            }
        }
    }

    // ---- cooperative loads (all warps) ----
    const float* xb = x + (size_t)b * (NG * ND * NL) + (size_t)g * ND * NL + l0g;
    const int ncols = min(TILE + 2, NL - l0g);
    for (int idx = t; idx < ND * XPAD; idx += 256) {
        int d = idx / XPAD, cc = idx % XPAD;
        xs[idx] = (cc < ncols) ? xb[(size_t)d * NL + cc] : 0.f;
    }
    // w1 transpose: w1t[(d*3+k)*64 + o] = w1[g][o][d][k]
    const float* w1g = w1 + (size_t)g * NOUT * ND * NKS;
    for (int idx = t; idx < NOUT * ND * NKS; idx += 256) {
        int o = idx / (ND * NKS), dk = idx % (ND * NKS);
        w1t[dk * NOUT + o] = w1g[idx];
    }
    if (t < NOUT) b1s[t] = b1[g * NOUT + t];
    __syncthreads();   // gates ready in gsm

    // ---- W_eff fold: wet[i*WETP+o] = sum_e gsm[e] * w2[g][o*E+e][i] ----
    float gv[NE];
    #pragma unroll
    for (int e = 0; e < NE; e++) gv[e] = gsm[e];
    const float* w2g = w2 + (size_t)g * NOUT * NE * NOUT;
    #pragma unroll
    for (int it = 0; it < (NOUT * NOUT) / 256; it++) {
        int idx = t + it * 256;
        int o = idx >> 6, i = idx & 63;
        const float* wrow = w2g + (size_t)o * NE * NOUT + i;
        float acc = 0.f;
        #pragma unroll
        for (int e = 0; e < NE; e++) acc += gv[e] * wrow[e * NOUT];
        wet[i * WETP + o] = acc;
    }
    if (t < NOUT) {
        const float* brow = b2 + (size_t)g * NOUT * NE + t * NE;
        float acc = 0.f;
        #pragma unroll
        for (int e = 0; e < NE; e++) acc += gv[e] * brow[e];
        bes[t] = acc;
    }
    __syncthreads();

    // ---- phase 2: h = tanh(conv1(x)), FFMA2 over channel pairs ----
    {
        u64 acc2[4][4];
        #pragma unroll
        for (int i2 = 0; i2 < 4; i2++) {
            u64 bv = *(const u64*)&b1s[ob + 2 * i2];
            #pragma unroll
            for (int j = 0; j < 4; j++) acc2[i2][j] = bv;
        }
        #pragma unroll
        for (int d = 0; d < ND; d++) {
            const float4 xa = *(const float4*)&xs[d * XPAD + l0];
            const float4 xc = *(const float4*)&xs[d * XPAD + l0 + 4];
            u64 xd[6];
            xd[0] = pack_dup(xa.x); xd[1] = pack_dup(xa.y);
            xd[2] = pack_dup(xa.z); xd[3] = pack_dup(xa.w);
            xd[4] = pack_dup(xc.x); xd[5] = pack_dup(xc.y);
            #pragma unroll
            for (int k = 0; k < NKS; k++) {
                const ulonglong2 wp0 = *(const ulonglong2*)&w1t[(d * NKS + k) * NOUT + ob];
                const ulonglong2 wp1 = *(const ulonglong2*)&w1t[(d * NKS + k) * NOUT + ob + 4];
                const u64 wp[4] = {wp0.x, wp0.y, wp1.x, wp1.y};
                #pragma unroll
                for (int i2 = 0; i2 < 4; i2++) {
                    ffma2(acc2[i2][0], wp[i2], xd[k + 0]);
                    ffma2(acc2[i2][1], wp[i2], xd[k + 1]);
                    ffma2(acc2[i2][2], wp[i2], xd[k + 2]);
                    ffma2(acc2[i2][3], wp[i2], xd[k + 3]);
                }
            }
        }
        #pragma unroll
        for (int i2 = 0; i2 < 4; i2++) {
            float2 v0 = unpack2(acc2[i2][0]);
            float2 v1 = unpack2(acc2[i2][1]);
            float2 v2 = unpack2(acc2[i2][2]);
            float2 v3 = unpack2(acc2[i2][3]);
            *(float4*)&hs[(ob + 2 * i2) * TILE + l0] =
                make_float4(tanh_fast(v0.x), tanh_fast(v1.x),
                            tanh_fast(v2.x), tanh_fast(v3.x));
            *(float4*)&hs[(ob + 2 * i2 + 1) * TILE + l0] =
                make_float4(tanh_fast(v0.y), tanh_fast(v1.y),
                            tanh_fast(v2.y), tanh_fast(v3.y));
        }
    }
    __syncthreads();

    // ---- phase 3: out = W_eff @ h + b_eff, FFMA2 over channel pairs ----
    u64 acc2[4][4];
    #pragma unroll
    for (int i2 = 0; i2 < 4; i2++) {
        u64 bv = *(const u64*)&bes[ob + 2 * i2];
        #pragma unroll
        for (int j = 0; j < 4; j++) acc2[i2][j] = bv;
    }
    #pragma unroll 4
    for (int k = 0; k < NOUT; k++) {
        const float4 hv = *(const float4*)&hs[k * TILE + l0];
        u64 hd[4];
        hd[0] = pack_dup(hv.x); hd[1] = pack_dup(hv.y);
        hd[2] = pack_dup(hv.z); hd[3] = pack_dup(hv.w);
        const ulonglong2 wp0 = *(const ulonglong2*)&wet[k * WETP + ob];
        const ulonglong2 wp1 = *(const ulonglong2*)&wet[k * WETP + ob + 4];
        const u64 wp[4] = {wp0.x, wp0.y, wp1.x, wp1.y};
        #pragma unroll
        for (int i2 = 0; i2 < 4; i2++) {
            ffma2(acc2[i2][0], wp[i2], hd[0]);
            ffma2(acc2[i2][1], wp[i2], hd[1]);
            ffma2(acc2[i2][2], wp[i2], hd[2]);
            ffma2(acc2[i2][3], wp[i2], hd[3]);
        }
    }

    // store (combine_features: (B, G, OUT, LP)); rows only 8B-aligned -> float2
    #pragma unroll
    for (int i2 = 0; i2 < 4; i2++) {
        float2 v0 = unpack2(acc2[i2][0]);
        float2 v1 = unpack2(acc2[i2][1]);
        float2 v2 = unpack2(acc2[i2][2]);
        float2 v3 = unpack2(acc2[i2][3]);
        float* row0 = out + ((size_t)(b * NG + g) * NOUT + (ob + 2 * i2)) * NLP + l0g + l0;
        float* row1 = row0 + NLP;
        if (tlen == TILE) {
            *(float2*)(row0)     = make_float2(v0.x, v1.x);
            *(float2*)(row0 + 2) = make_float2(v2.x, v3.x);
            *(float2*)(row1)     = make_float2(v0.y, v1.y);
            *(float2*)(row1 + 2) = make_float2(v2.y, v3.y);
        } else {
            float a0[4] = {v0.x, v1.x, v2.x, v3.x};
            float a1[4] = {v0.y, v1.y, v2.y, v3.y};
            #pragma unroll
            for (int j = 0; j < 4; j++)
                if (l0 + j < tlen) { row0[j] = a0[j]; row1[j] = a1[j]; }
        }
    }
}

// ---------------------------------------------------------------------------
extern "C" void kernel_launch(void* const* d_in, const int* in_sizes, int n_in,
                              void* d_out, int out_size) {
    const float* x       = (const float*)d_in[0];
    const float* w_gate  = (const float*)d_in[1];
    const float* conv1_w = (const float*)d_in[2];
    const float* conv1_b = (const float*)d_in[3];
    const float* conv2_w = (const float*)d_in[4];
    const float* conv2_b = (const float*)d_in[5];
    float* out = (float*)d_out;

    const int smem_bytes = (ND * XPAD + ND * NKS * NOUT + NOUT * WETP
                            + NOUT * TILE + 2 * NOUT + NE) * sizeof(float);
    cudaFuncSetAttribute(main_kernel,
                         cudaFuncAttributeMaxDynamicSharedMemorySize, smem_bytes);

    main_kernel<<<dim3(NTILES, NB, NG), 256, smem_bytes>>>(
        x, w_gate, conv1_w, conv1_b, conv2_w, conv2_b, out);
    loss_kernel<<<1, 64>>>(out);
}

// round 6
// speedup vs baseline: 1.8829x; 1.1681x over previous
#include <cuda_runtime.h>
#include <math.h>

#define NG   8
#define ND   16
#define NL   1024
#define NB   16
#define NE   8
#define NOUT 64
#define NKS  3
#define NK   4
#define NLP  1022
#define TILE 128
#define NTILES 8
#define XPAD 132
#define WETP 72            // W_eff row stride: 72%32=8 -> conflict-free frag loads
#define HSP  136           // h row stride:    136%32=8 -> conflict-free frag loads

typedef unsigned long long u64;
typedef unsigned int u32;

// Scratch (static device global — no allocation)
__device__ float g_gates[NG*NB*NE];

__device__ __forceinline__ float tanh_fast(float x) {
    float r;
    asm("tanh.approx.f32 %0, %1;" : "=f"(r) : "f"(x));
    return r;
}
__device__ __forceinline__ float round_tf32(float x) {
    u32 r;
    asm("cvt.rna.tf32.f32 %0, %1;" : "=r"(r) : "f"(x));
    return __uint_as_float(r);
}
// packed f32x2 fma (kept from R5: measured neutral, zero downside)
__device__ __forceinline__ void ffma2(u64& d, u64 a, u64 b) {
    asm("fma.rn.f32x2 %0, %1, %2, %0;" : "+l"(d) : "l"(a), "l"(b));
}
__device__ __forceinline__ u64 pack_dup(float x) {
    u64 r; asm("mov.b64 %0, {%1, %1};" : "=l"(r) : "f"(x)); return r;
}
__device__ __forceinline__ float2 unpack2(u64 v) {
    float2 f; asm("mov.b64 {%0, %1}, %2;" : "=f"(f.x), "=f"(f.y) : "l"(v)); return f;
}
// tf32 mma: D(16x8) = A(16x8) @ B(8x8) + D
__device__ __forceinline__ void mma_tf32(float& c0, float& c1, float& c2, float& c3,
                                         u32 a0, u32 a1, u32 a2, u32 a3,
                                         u32 b0, u32 b1) {
    asm("mma.sync.aligned.m16n8k8.row.col.f32.tf32.tf32.f32 "
        "{%0,%1,%2,%3}, {%4,%5,%6,%7}, {%8,%9}, {%0,%1,%2,%3};"
        : "+f"(c0), "+f"(c1), "+f"(c2), "+f"(c3)
        : "r"(a0), "r"(a1), "r"(a2), "r"(a3), "r"(b0), "r"(b1));
}

__device__ __forceinline__ float cv_sq(const float* v) {
    float m = 0.f;
    #pragma unroll
    for (int i = 0; i < NE; i++) m += v[i];
    m *= (1.f / NE);
    float var = 0.f;
    #pragma unroll
    for (int i = 0; i < NE; i++) { float d = v[i] - m; var += d * d; }
    var *= (1.f / (NE - 1));
    return var / (m * m + 1e-10f);
}

// ---------------------------------------------------------------------------
// loss kernel (trailing): parallel loads, 64 threads.
// ---------------------------------------------------------------------------
__global__ void loss_kernel(float* __restrict__ out) {
    const int t = threadIdx.x;
    __shared__ float s_imp[NG][NE];
    __shared__ float s_ld[NG][NE];
    __shared__ float lsum[NG];
    if (t < NG * NE) {
        const int g = t >> 3, e = t & 7;
        float imp = 0.f, ld = 0.f;
        #pragma unroll
        for (int bb = 0; bb < NB; bb++) {
            float v = g_gates[((g * NB + bb) * NE) + e];
            imp += v;
            ld  += (v > 0.f) ? 1.f : 0.f;
        }
        s_imp[g][e] = imp;
        s_ld[g][e]  = ld;
    }
    __syncthreads();
    if (t < NG) lsum[t] = cv_sq(s_imp[t]) + cv_sq(s_ld[t]);
    __syncthreads();
    if (t == 0) {
        float total = 0.f;
        #pragma unroll
        for (int i = 0; i < NG; i++) total += lsum[i];
        out[(size_t)NB * NG * NOUT * NLP] = 0.01f * total;
    }
}

// ---------------------------------------------------------------------------
// Main kernel: gates (warp 0) + W_eff fold + conv1(fp32)+tanh + tf32-MMA GEMM.
// grid (NTILES, NB, NG), 256 threads.
// ---------------------------------------------------------------------------
__global__ __launch_bounds__(256)
void main_kernel(const float* __restrict__ x,
                 const float* __restrict__ w_gate,
                 const float* __restrict__ w1,
                 const float* __restrict__ b1,
                 const float* __restrict__ w2,
                 const float* __restrict__ b2,
                 float* __restrict__ out) {
    const int tile = blockIdx.x;
    const int b    = blockIdx.y;
    const int g    = blockIdx.z;
    const int l0g  = tile * TILE;
    const int tlen = min(TILE, NLP - l0g);

    extern __shared__ float smem[];
    float* xs  = smem;                         // ND * XPAD       = 2112
    float* w1t = xs  + ND * XPAD;              // [d*3+k][o]      = 3072
    float* wet = w1t + ND * NKS * NOUT;        // [k][o] pad 72   = 4608 (tf32)
    float* hs  = wet + NOUT * WETP;            // [k][l] pad 136  = 8704 (tf32)
    float* bes = hs  + NOUT * HSP;             // 64
    float* b1s = bes + NOUT;                   // 64
    float* gsm = b1s + NOUT;                   // 8 gates

    const int t = threadIdx.x;
    const int c = t & 31;          // lane
    const int r = t >> 5;          // warp id
    const int ob = r * 8;          // phase-2: 8 contiguous output channels
    const int l0 = c * 4;          // phase-2: 4 columns

    // ---- warp 0: compute gates for (g,b) ----
    if (r == 0) {
        float plog[NE];
        #pragma unroll
        for (int e = 0; e < NE; e++) plog[e] = 0.f;
        #pragma unroll
        for (int i = c; i < ND * 5; i += 32) {
            int d = i / 5, j = i % 5;
            float xv = x[(size_t)b * (NG * ND * NL) + (size_t)(g * ND + d) * NL + (NL - 6 + j)];
            const float4* w4 = (const float4*)(w_gate + ((size_t)g * ND * 5 + i) * NE);
            float4 wa = w4[0], wb = w4[1];
            plog[0] += xv * wa.x; plog[1] += xv * wa.y;
            plog[2] += xv * wa.z; plog[3] += xv * wa.w;
            plog[4] += xv * wb.x; plog[5] += xv * wb.y;
            plog[6] += xv * wb.z; plog[7] += xv * wb.w;
        }
        #pragma unroll
        for (int off = 16; off >= 1; off >>= 1)
            #pragma unroll
            for (int e = 0; e < NE; e++)
                plog[e] += __shfl_xor_sync(0xffffffffu, plog[e], off);

        if (c == 0) {
            float m = plog[0];
            #pragma unroll
            for (int e = 1; e < NE; e++) m = fmaxf(m, plog[e]);
            float p[NE]; float s = 0.f;
            #pragma unroll
            for (int e = 0; e < NE; e++) { p[e] = __expf(plog[e] - m); s += p[e]; }
            float inv = 1.f / s;
            #pragma unroll
            for (int e = 0; e < NE; e++) p[e] *= inv;

            float q[NE];
            #pragma unroll
            for (int e = 0; e < NE; e++) q[e] = p[e];
            float tv[NK]; int ti[NK];
            #pragma unroll
            for (int k = 0; k < NK; k++) {
                float best = -1e30f; int bi = 0;
                #pragma unroll
                for (int e = 0; e < NE; e++)
                    if (q[e] > best) { best = q[e]; bi = e; }
                tv[k] = best; ti[k] = bi; q[bi] = -1e30f;
            }
            float dsum = tv[0] + tv[1] + tv[2] + tv[3] + 1e-6f;
            float gates[NE];
            #pragma unroll
            for (int e = 0; e < NE; e++) gates[e] = 0.f;
            #pragma unroll
            for (int k = 0; k < NK; k++) gates[ti[k]] = tv[k] / dsum;

            #pragma unroll
            for (int e = 0; e < NE; e++) gsm[e] = gates[e];
            if (tile == 0) {
                const size_t combine_sz = (size_t)NB * NG * NOUT * NLP;
                #pragma unroll
                for (int e = 0; e < NE; e++) {
                    g_gates[(g * NB + b) * NE + e] = gates[e];
                    out[combine_sz + 1 + (size_t)(b * NE + e) * NG + g] = gates[e];
                }
            }
        }
    }

    // ---- cooperative loads (all warps) ----
    const float* xb = x + (size_t)b * (NG * ND * NL) + (size_t)g * ND * NL + l0g;
    const int ncols = min(TILE + 2, NL - l0g);
    for (int idx = t; idx < ND * XPAD; idx += 256) {
        int d = idx / XPAD, cc = idx % XPAD;
        xs[idx] = (cc < ncols) ? xb[(size_t)d * NL + cc] : 0.f;
    }
    // w1 transpose: w1t[(d*3+k)*64 + o] = w1[g][o][d][k]
    const float* w1g = w1 + (size_t)g * NOUT * ND * NKS;
    for (int idx = t; idx < NOUT * ND * NKS; idx += 256) {
        int o = idx / (ND * NKS), dk = idx % (ND * NKS);
        w1t[dk * NOUT + o] = w1g[idx];
    }
    if (t < NOUT) b1s[t] = b1[g * NOUT + t];
    __syncthreads();   // gates ready in gsm

    // ---- W_eff fold (tf32-rounded): wet[k*WETP+o] = sum_e g[e]*w2[g][o*E+e][k]
    float gv[NE];
    #pragma unroll
    for (int e = 0; e < NE; e++) gv[e] = gsm[e];
    const float* w2g = w2 + (size_t)g * NOUT * NE * NOUT;
    #pragma unroll
    for (int it = 0; it < (NOUT * NOUT) / 256; it++) {
        int idx = t + it * 256;
        int o = idx >> 6, i = idx & 63;
        const float* wrow = w2g + (size_t)o * NE * NOUT + i;
        float acc = 0.f;
        #pragma unroll
        for (int e = 0; e < NE; e++) acc += gv[e] * wrow[e * NOUT];
        wet[i * WETP + o] = round_tf32(acc);
    }
    if (t < NOUT) {
        const float* brow = b2 + (size_t)g * NOUT * NE + t * NE;
        float acc = 0.f;
        #pragma unroll
        for (int e = 0; e < NE; e++) acc += gv[e] * brow[e];
        bes[t] = acc;
    }
    __syncthreads();

    // ---- phase 2: h = tanh(conv1(x)) in fp32 (FFMA2), tf32-rounded store ----
    {
        u64 acc2[4][4];
        #pragma unroll
        for (int i2 = 0; i2 < 4; i2++) {
            u64 bv = *(const u64*)&b1s[ob + 2 * i2];
            #pragma unroll
            for (int j = 0; j < 4; j++) acc2[i2][j] = bv;
        }
        #pragma unroll
        for (int d = 0; d < ND; d++) {
            const float4 xa = *(const float4*)&xs[d * XPAD + l0];
            const float4 xc = *(const float4*)&xs[d * XPAD + l0 + 4];
            u64 xd[6];
            xd[0] = pack_dup(xa.x); xd[1] = pack_dup(xa.y);
            xd[2] = pack_dup(xa.z); xd[3] = pack_dup(xa.w);
            xd[4] = pack_dup(xc.x); xd[5] = pack_dup(xc.y);
            #pragma unroll
            for (int k = 0; k < NKS; k++) {
                const ulonglong2 wp0 = *(const ulonglong2*)&w1t[(d * NKS + k) * NOUT + ob];
                const ulonglong2 wp1 = *(const ulonglong2*)&w1t[(d * NKS + k) * NOUT + ob + 4];
                const u64 wp[4] = {wp0.x, wp0.y, wp1.x, wp1.y};
                #pragma unroll
                for (int i2 = 0; i2 < 4; i2++) {
                    ffma2(acc2[i2][0], wp[i2], xd[k + 0]);
                    ffma2(acc2[i2][1], wp[i2], xd[k + 1]);
                    ffma2(acc2[i2][2], wp[i2], xd[k + 2]);
                    ffma2(acc2[i2][3], wp[i2], xd[k + 3]);
                }
            }
        }
        #pragma unroll
        for (int i2 = 0; i2 < 4; i2++) {
            float2 v0 = unpack2(acc2[i2][0]);
            float2 v1 = unpack2(acc2[i2][1]);
            float2 v2 = unpack2(acc2[i2][2]);
            float2 v3 = unpack2(acc2[i2][3]);
            *(float4*)&hs[(ob + 2 * i2) * HSP + l0] =
                make_float4(round_tf32(tanh_fast(v0.x)), round_tf32(tanh_fast(v1.x)),
                            round_tf32(tanh_fast(v2.x)), round_tf32(tanh_fast(v3.x)));
            *(float4*)&hs[(ob + 2 * i2 + 1) * HSP + l0] =
                make_float4(round_tf32(tanh_fast(v0.y)), round_tf32(tanh_fast(v1.y)),
                            round_tf32(tanh_fast(v2.y)), round_tf32(tanh_fast(v3.y)));
        }
    }
    __syncthreads();

    // ---- phase 3: out = W_eff @ h + b_eff via tf32 mma.sync (m16n8k8) ----
    // warp r -> mt = r&3 (16 o-rows at mt*16), nh = r>>2 (64 cols at nh*64)
    // A(16x8) = W[o][k] from wet[k*WETP+o]; B(8x8) = h[k][n] from hs[k*HSP+n]
    {
        const int mt = r & 3;
        const int nh = r >> 2;
        const int gid = c >> 2;      // 0..7
        const int tg  = c & 3;       // 0..3
        const int orow0 = mt * 16 + gid;

        float cacc[8][4];
        const float bv0 = bes[orow0];
        const float bv1 = bes[orow0 + 8];
        #pragma unroll
        for (int nt = 0; nt < 8; nt++) {
            cacc[nt][0] = bv0; cacc[nt][1] = bv0;
            cacc[nt][2] = bv1; cacc[nt][3] = bv1;
        }

        const u32* wetu = (const u32*)wet;
        const u32* hsu  = (const u32*)hs;
        #pragma unroll
        for (int kt = 0; kt < 8; kt++) {
            const int k0 = kt * 8;
            // A frag: a0=(row gid, col tg) a1=(row gid+8, col tg) a2=(gid, tg+4) a3=(gid+8, tg+4)
            const u32 a0 = wetu[(k0 + tg) * WETP + orow0];
            const u32 a1 = wetu[(k0 + tg) * WETP + orow0 + 8];
            const u32 a2 = wetu[(k0 + tg + 4) * WETP + orow0];
            const u32 a3 = wetu[(k0 + tg + 4) * WETP + orow0 + 8];
            #pragma unroll
            for (int nt = 0; nt < 8; nt++) {
                const int ncol = nh * 64 + nt * 8 + gid;
                // B frag: b0=(row tg, col gid) b1=(row tg+4, col gid)
                const u32 b0 = hsu[(k0 + tg) * HSP + ncol];
                const u32 b1 = hsu[(k0 + tg + 4) * HSP + ncol];
                mma_tf32(cacc[nt][0], cacc[nt][1], cacc[nt][2], cacc[nt][3],
                         a0, a1, a2, a3, b0, b1);
            }
        }

        // store: c0/c1 at (row orow0, cols tg*2, tg*2+1); c2/c3 at row orow0+8
        #pragma unroll
        for (int nt = 0; nt < 8; nt++) {
            const int colt = nh * 64 + nt * 8 + tg * 2;   // col within tile (even)
            float* row0 = out + ((size_t)(b * NG + g) * NOUT + orow0) * NLP + l0g + colt;
            float* row1 = out + ((size_t)(b * NG + g) * NOUT + orow0 + 8) * NLP + l0g + colt;
            if (colt + 1 < tlen) {
                *(float2*)row0 = make_float2(cacc[nt][0], cacc[nt][1]);
                *(float2*)row1 = make_float2(cacc[nt][2], cacc[nt][3]);
            } else if (colt < tlen) {
                row0[0] = cacc[nt][0];
                row1[0] = cacc[nt][2];
            }
        }
    }
}

// ---------------------------------------------------------------------------
extern "C" void kernel_launch(void* const* d_in, const int* in_sizes, int n_in,
                              void* d_out, int out_size) {
    const float* x       = (const float*)d_in[0];
    const float* w_gate  = (const float*)d_in[1];
    const float* conv1_w = (const float*)d_in[2];
    const float* conv1_b = (const float*)d_in[3];
    const float* conv2_w = (const float*)d_in[4];
    const float* conv2_b = (const float*)d_in[5];
    float* out = (float*)d_out;

    const int smem_bytes = (ND * XPAD + ND * NKS * NOUT + NOUT * WETP
                            + NOUT * HSP + 2 * NOUT + NE) * sizeof(float);
    cudaFuncSetAttribute(main_kernel,
                         cudaFuncAttributeMaxDynamicSharedMemorySize, smem_bytes);

    main_kernel<<<dim3(NTILES, NB, NG), 256, smem_bytes>>>(
        x, w_gate, conv1_w, conv1_b, conv2_w, conv2_b, out);
    loss_kernel<<<1, 64>>>(out);
}